// round 5
// baseline (speedup 1.0000x reference)
#include <cuda_runtime.h>
#include <cuda_fp16.h>

// RoIAlign1D: B=8, LV=4096, D=256, N=2048 boxes, P=32 bins.
// R4: issue-bound -> widen to 8 channels/thread (one warp covers a full
// 256-ch row via LDG.128 of 8 halves). 64-thread block = 2 row streams
// (even/odd rows), combined through smem at the end.

#define B_   8
#define LV_  4096
#define D_   256
#define N_   2048
#define P_   32
#define WIN_ 144   // max rows per bin window: bin_h<=128 -> <=130 rows + slack

// 16 MB fp16 copy of feat (static device scratch; no allocation APIs used)
__device__ __half g_feat16[B_ * LV_ * D_];

// ---- pre-pass: f32 -> f16, 8 floats per thread, fully coalesced ----
__global__ __launch_bounds__(256) void cvt_kernel(const float* __restrict__ feat)
{
    const int i = blockIdx.x * 256 + threadIdx.x;       // uint4 (8-half) index
    const float4* src = reinterpret_cast<const float4*>(feat) + 2 * (size_t)i;
    float4 v0 = src[0];
    float4 v1 = src[1];
    __half2 h0 = __floats2half2_rn(v0.x, v0.y);
    __half2 h1 = __floats2half2_rn(v0.z, v0.w);
    __half2 h2 = __floats2half2_rn(v1.x, v1.y);
    __half2 h3 = __floats2half2_rn(v1.z, v1.w);
    uint4 o;
    o.x = *reinterpret_cast<unsigned int*>(&h0);
    o.y = *reinterpret_cast<unsigned int*>(&h1);
    o.z = *reinterpret_cast<unsigned int*>(&h2);
    o.w = *reinterpret_cast<unsigned int*>(&h3);
    reinterpret_cast<uint4*>(g_feat16)[i] = o;
}

__global__ __launch_bounds__(64) void roi_align1d_kernel(
    const float* __restrict__ boxes,   // [N, 2]
    const int*   __restrict__ bidx,    // [N]
    float*       __restrict__ out)     // [N, P, D]
{
    __shared__ float w_s[WIN_];
    __shared__ float part_s[D_];       // warp-1 partials for the combine
    __shared__ int   rmin_s, rmax_s;

    const int blk  = blockIdx.x;       // 0 .. N*P-1
    const int n    = blk >> 5;         // box
    const int p    = blk & (P_ - 1);   // bin
    const int tid  = threadIdx.x;      // 0..63
    const int wid  = tid >> 5;         // 0,1
    const int lane = tid & 31;

    // ---- zero the weight window ----
    #pragma unroll
    for (int i = tid; i < WIN_; i += 64) w_s[i] = 0.0f;
    if (tid == 0) { rmin_s = 0x7fffffff; rmax_s = -1; }

    // ---- box scalars (redundant per thread; L1-hot) ----
    const float y1    = boxes[2 * n];
    const float y2    = boxes[2 * n + 1];
    const float roi_h = y2 - y1;
    const float bin_h = roi_h * (1.0f / (float)P_);   // exact: /32
    const int   grid_h = (int)ceilf(bin_h);
    const int   cnt    = max(grid_h, 1);
    const float sub    = bin_h / (float)cnt;
    const float bin_off = (y1 - 0.5f) + (float)p * bin_h;

    int rb = (int)floorf(bin_off);
    rb = max(rb, 0);
    rb = min(rb, LV_ - 1);

    __syncthreads();

    // ---- Phase A: collapse samples into per-row bilinear weights ----
    for (int g = tid; g < grid_h; g += 64) {
        float y = bin_off + ((float)g + 0.5f) * sub;
        if (y >= -1.0f && y <= (float)LV_) {
            float yc = fmaxf(y, 0.0f);
            int ylo = (int)floorf(yc);
            int yhi;
            float ly;
            if (ylo >= LV_ - 1) {            // hi_case from reference
                ylo = LV_ - 1;
                yhi = LV_ - 1;
                ly  = 0.0f;
            } else {
                yhi = ylo + 1;
                ly  = yc - (float)ylo;
            }
            int i0 = ylo - rb;
            int i1 = yhi - rb;
            i0 = min(max(i0, 0), WIN_ - 1);  // guards smem; mathematically no-op
            i1 = min(max(i1, 0), WIN_ - 1);
            atomicAdd(&w_s[i0], 1.0f - ly);
            atomicAdd(&w_s[i1], ly);
            atomicMin(&rmin_s, ylo);
            atomicMax(&rmax_s, yhi);
        }
    }
    __syncthreads();

    int rmin = rmin_s;
    int rmax = rmax_s;
    if (rmax < rmin) { rmin = 0; rmax = -1; }   // empty bin

    const float invc = 1.0f / (float)cnt;
    const int   base = bidx[n] * LV_;

    // ---- Phase B: warp = full row (32 lanes x 8 halves = 256 ch).
    //      warp 0 -> rows rmin, rmin+2, ...; warp 1 -> rmin+1, rmin+3, ...
    float a0 = 0.f, a1 = 0.f, a2 = 0.f, a3 = 0.f;
    float a4 = 0.f, a5 = 0.f, a6 = 0.f, a7 = 0.f;

    const int r0 = rmin + wid;
    const uint4* fp = reinterpret_cast<const uint4*>(g_feat16)
                    + (size_t)(base + r0) * (D_ / 8) + lane;

    #pragma unroll 2
    for (int r = r0; r <= rmax; r += 2) {
        const float wr = w_s[r - rb];
        uint4 u = *fp;
        fp += 2 * (D_ / 8);
        float2 v0 = __half22float2(*reinterpret_cast<__half2*>(&u.x));
        float2 v1 = __half22float2(*reinterpret_cast<__half2*>(&u.y));
        float2 v2 = __half22float2(*reinterpret_cast<__half2*>(&u.z));
        float2 v3 = __half22float2(*reinterpret_cast<__half2*>(&u.w));
        a0 = fmaf(wr, v0.x, a0);
        a1 = fmaf(wr, v0.y, a1);
        a2 = fmaf(wr, v1.x, a2);
        a3 = fmaf(wr, v1.y, a3);
        a4 = fmaf(wr, v2.x, a4);
        a5 = fmaf(wr, v2.y, a5);
        a6 = fmaf(wr, v3.x, a6);
        a7 = fmaf(wr, v3.y, a7);
    }

    // ---- combine the two row streams ----
    if (wid == 1) {
        float4* ps = reinterpret_cast<float4*>(part_s) + lane * 2;
        ps[0] = make_float4(a0, a1, a2, a3);
        ps[1] = make_float4(a4, a5, a6, a7);
    }
    __syncthreads();
    if (wid == 0) {
        const float4* ps = reinterpret_cast<const float4*>(part_s) + lane * 2;
        float4 p0 = ps[0];
        float4 p1 = ps[1];
        float4 o0, o1;
        o0.x = (a0 + p0.x) * invc;
        o0.y = (a1 + p0.y) * invc;
        o0.z = (a2 + p0.z) * invc;
        o0.w = (a3 + p0.w) * invc;
        o1.x = (a4 + p1.x) * invc;
        o1.y = (a5 + p1.y) * invc;
        o1.z = (a6 + p1.z) * invc;
        o1.w = (a7 + p1.w) * invc;
        float4* op = reinterpret_cast<float4*>(out) + (size_t)blk * (D_ / 4) + lane * 2;
        op[0] = o0;
        op[1] = o1;
    }
}

extern "C" void kernel_launch(void* const* d_in, const int* in_sizes, int n_in,
                              void* d_out, int out_size)
{
    const float* feat  = (const float*)d_in[0];   // [8, 4096, 256] f32
    const float* boxes = (const float*)d_in[1];   // [2048, 2] f32
    const int*   bidx  = (const int*)  d_in[2];   // [2048] i32
    float*       out   = (float*)d_out;           // [2048, 32, 256] f32

    // 8.39M halves / 8 per thread = 1,048,576 threads -> 4096 blocks x 256
    cvt_kernel<<<(B_ * LV_ * D_ / 8) / 256, 256>>>(feat);
    roi_align1d_kernel<<<N_ * P_, 64>>>(boxes, bidx, out);
}